// round 6
// baseline (speedup 1.0000x reference)
#include <cuda_runtime.h>
#include <cuda_bf16.h>

// ShiftingLayer: out[b,d,c] = (1/AMP) * sum_s exp(-(s - center[b,d])^2) * in[b,s,c]
//   center[b,d] = (d+1 + w[b,d]) * (S/D), s = 1..S (1-indexed).
//
// Per-d private window of K=8 rows around floor(center); omitted weights
// <= exp(-16) ~ 1.1e-7 relative. float4 vectorized, weights computed in
// registers (no smem / no syncthreads). DT=4 d's per 256-thread block ->
// grid 4096 -> ~7 full waves at 4 blocks/SM (tail waste ~1%).

#define B_ 16
#define S_ 4096
#define C_ 256
#define D_ 1024

constexpr int   DT      = 4;          // d's per block (one per 64-thread group)
constexpr int   K_      = 8;          // window rows per d
constexpr int   RAD     = 3;          // floor(c)-RAD .. floor(c)-RAD+K-1
constexpr float SCALE   = (float)S_ / (float)D_;   // 4.0
constexpr float INV_AMP = 1.0f / 1.772637204826652f;

__global__ __launch_bounds__(256, 4)
void ShiftingLayer_53798760349850_kernel(const float* __restrict__ in,
                                         const float* __restrict__ wts,
                                         float* __restrict__ out) {
    const int tid = threadIdx.x;
    const int b   = blockIdx.x / (D_ / DT);
    const int d   = (blockIdx.x % (D_ / DT)) * DT + (tid >> 6);  // this thread's d
    const int cq  = tid & 63;                                    // channel quad

    // Window start (address-only dependency: lets loads issue before __expf)
    const float w  = __ldg(&wts[b * D_ + d]);        // broadcast within group
    const float c  = ((float)(d + 1) + w) * SCALE;
    int ss = (int)floorf(c) - RAD;                   // 1-indexed window start
    if (ss < 1) ss = 1;
    if (ss > S_ - K_ + 1) ss = S_ - K_ + 1;

    const float4* p = reinterpret_cast<const float4*>(in) +
                      (size_t)b * S_ * (C_ / 4) + (size_t)(ss - 1) * (C_ / 4) + cq;

    // Issue all 8 input loads (independent, LDG.128, MLP=8)
    float4 x[K_];
#pragma unroll
    for (int k = 0; k < K_; k++)
        x[k] = p[(size_t)k * (C_ / 4)];

    // Per-thread Gaussian weights (MUFU, overlapped with load latency)
    float wk[K_];
#pragma unroll
    for (int k = 0; k < K_; k++) {
        const float diff = (float)(ss + k) - c;
        wk[k] = __expf(-diff * diff);
    }

    float4 acc = make_float4(0.f, 0.f, 0.f, 0.f);
#pragma unroll
    for (int k = 0; k < K_; k++) {
        acc.x = fmaf(wk[k], x[k].x, acc.x);
        acc.y = fmaf(wk[k], x[k].y, acc.y);
        acc.z = fmaf(wk[k], x[k].z, acc.z);
        acc.w = fmaf(wk[k], x[k].w, acc.w);
    }
    acc.x *= INV_AMP; acc.y *= INV_AMP; acc.z *= INV_AMP; acc.w *= INV_AMP;

    reinterpret_cast<float4*>(out)[((size_t)b * D_ + d) * (C_ / 4) + cq] = acc;
}

extern "C" void kernel_launch(void* const* d_in, const int* in_sizes, int n_in,
                              void* d_out, int out_size) {
    const float* in  = (const float*)d_in[0];   // (16, 4096, 256) f32
    const float* wts = (const float*)d_in[1];   // (16, 1024) f32
    float*       out = (float*)d_out;           // (16, 1024, 256) f32

    dim3 grid(B_ * (D_ / DT));   // 4096
    dim3 block(256);
    ShiftingLayer_53798760349850_kernel<<<grid, block>>>(in, wts, out);
}